// round 11
// baseline (speedup 1.0000x reference)
#include <cuda_runtime.h>

// GAT layer, shapes fixed: n=16, t=12, N=64, c=o=64. adj dead code.
// Verified algebra (R1-R9, rel_err ~4e-7):
//   tt<6 : e-row has 2 distinct values -> closed-form softmax over
//          r[T,u] = inp-row . (W@(a0+a1)); h' = aL*S_L + aH*S_H,
//          S_{L/H} = colsum(XC half) @ W.
//   tt>=6: e[v,w] = pe[w%32] + qo[w%32] per v-half -> 32-value softmax;
//          h' = (s @ Y) @ W with Y[j,c] = XC[j,c]+XC[j+32,c].
// R11 = R7 reverted (best passing config; ncu 8.51us, bench at the ~10.72us
// environment floor). cp.async variant (R10) failed: 16B cp.async needs 16B-
// aligned smem dst, incompatible with the conflict-free stride-65 layout.

#define NT 12
#define LRELU_A 0.2f
#define TS 65

struct Smem {
    float Ws[64 * TS];                  // Ws[c*TS+o] = W[c][o]
    float X0[64 * TS], X1[64 * TS], XC[64 * TS];
    float Y[32 * TS];                   // second branch: XC row-fold
    float a_s[128];
    float wa0[64], wa1[64];             // first branch uses wa0 = W@(a0+a1)
    float r0[64], r1[64];
    float v0[64], v1[64];
    float s0[64], s1[64];
    float h0[64], h1[64];
};

__device__ __forceinline__ float wsum(float v) {
#pragma unroll
    for (int s = 16; s; s >>= 1) v += __shfl_xor_sync(0xffffffffu, v, s);
    return v;
}
__device__ __forceinline__ float wmax(float v) {
#pragma unroll
    for (int s = 16; s; s >>= 1) v = fmaxf(v, __shfl_xor_sync(0xffffffffu, v, s));
    return v;
}
__device__ __forceinline__ float lrelu(float x) { return x > 0.0f ? x : LRELU_A * x; }
__device__ __forceinline__ float felu(float x)  { return x > 0.0f ? x : __expf(x) - 1.0f; }
__device__ __forceinline__ void st4(float* b, float4 v) {
    b[0] = v.x; b[1] = v.y; b[2] = v.z; b[3] = v.w;
}

__global__ void __launch_bounds__(512) gat_kernel(
    const float* __restrict__ inp, const float* __restrict__ W,
    const float* __restrict__ a, float* __restrict__ out_h,
    float* __restrict__ out_att)
{
    extern __shared__ Smem S[];
    const int tid = threadIdx.x;
    const int b   = blockIdx.x;           // unit = nn*12 + tt
    const int tt  = b % NT;
    const int nn  = b / NT;

    const bool first = (tt < 6);
    const int  T0    = first ? 2 * tt : 2 * (tt - 6);
    const float* __restrict__ iT0 = inp + ((size_t)nn * NT + T0) * 4096;
    const float* __restrict__ iT1 = iT0 + 4096;
    const float* __restrict__ iC  = inp + ((size_t)nn * NT + tt) * 4096;

    // ---- load: 8 independent LDG.128 per thread (512 thr) ------------------
#pragma unroll
    for (int i = 0; i < 2; ++i) {
        int idx = tid * 4 + i * 2048;
        float4 w  = *reinterpret_cast<const float4*>(W   + idx);
        float4 v0 = *reinterpret_cast<const float4*>(iT0 + idx);
        float4 v1 = *reinterpret_cast<const float4*>(iT1 + idx);
        float4 vc = *reinterpret_cast<const float4*>(iC  + idx);
        int base = (idx >> 6) * TS + (idx & 63);
        st4(S->Ws + base, w);
        st4(S->X0 + base, v0);
        st4(S->X1 + base, v1);
        st4(S->XC + base, vc);
    }
    if (tid < 128) S->a_s[tid] = a[tid];
    __syncthreads();

    const size_t obase = (size_t)b * 4096;

    if (first) {
        // ---- stage A: wa = W@(a0+a1) (tid<64) || colsums (tid in [64,192)) --
        if (tid < 64) {
            int c = tid;
            const float* wr = S->Ws + c * TS;
            float d0 = 0.f, d1 = 0.f, d2 = 0.f, d3 = 0.f;
#pragma unroll
            for (int o = 0; o < 64; o += 4) {
                d0 = fmaf(wr[o + 0], S->a_s[o + 0] + S->a_s[o + 64], d0);
                d1 = fmaf(wr[o + 1], S->a_s[o + 1] + S->a_s[o + 65], d1);
                d2 = fmaf(wr[o + 2], S->a_s[o + 2] + S->a_s[o + 66], d2);
                d3 = fmaf(wr[o + 3], S->a_s[o + 3] + S->a_s[o + 67], d3);
            }
            S->wa0[c] = (d0 + d1) + (d2 + d3);
        } else if (tid < 192) {
            int c = tid & 63; bool hi = (tid >= 128);
            const float* base = S->XC + (hi ? 32 * TS : 0) + c;
            float s0 = 0.f, s1 = 0.f, s2 = 0.f, s3 = 0.f;
#pragma unroll
            for (int w = 0; w < 32; w += 4) {
                s0 += base[(w + 0) * TS]; s1 += base[(w + 1) * TS];
                s2 += base[(w + 2) * TS]; s3 += base[(w + 3) * TS];
            }
            (hi ? S->v1 : S->v0)[c] = (s0 + s1) + (s2 + s3);
        }
        __syncthreads();
        // ---- stage B: r-dots (tid<128) || S = v@W (tid in [128,256)) -------
        if (tid < 128) {
            int u = tid & 63;
            const float* row = ((tid < 64) ? S->X0 : S->X1) + u * TS;
            float a0 = 0.f, a1 = 0.f;
#pragma unroll
            for (int c = 0; c < 64; c += 2) {
                a0 = fmaf(row[c],     S->wa0[c],     a0);
                a1 = fmaf(row[c + 1], S->wa0[c + 1], a1);
            }
            ((tid < 64) ? S->r0 : S->r1)[u] = a0 + a1;
        } else if (tid < 256) {
            int o = tid & 63; bool hi = (tid >= 192);
            const float* vv = hi ? S->v1 : S->v0;
            float d0 = 0.f, d1 = 0.f, d2 = 0.f, d3 = 0.f;
#pragma unroll
            for (int c = 0; c < 64; c += 4) {
                d0 = fmaf(vv[c + 0], S->Ws[(c + 0) * TS + o], d0);
                d1 = fmaf(vv[c + 1], S->Ws[(c + 1) * TS + o], d1);
                d2 = fmaf(vv[c + 2], S->Ws[(c + 2) * TS + o], d2);
                d3 = fmaf(vv[c + 3], S->Ws[(c + 3) * TS + o], d3);
            }
            (hi ? S->h1 : S->h0)[o] = (d0 + d1) + (d2 + d3);
        }
        __syncthreads();
        // ---- stage C: closed-form softmax (tid<64) --------------------------
        if (tid < 64) {
            int v = tid;
            const float* rr = (v < 32) ? S->r0 : S->r1;
            float eL = lrelu(rr[(2 * v) & 63]);
            float eH = lrelu(rr[(2 * v + 1) & 63]);
            float m  = fmaxf(eL, eH);
            float wl = __expf(eL - m), wh = __expf(eH - m);
            float den = __fdividef(1.0f, 32.0f * (wl + wh));
            S->s0[v] = wl * den;
            S->s1[v] = wh * den;
        }
        __syncthreads();
        // ---- write: 512 thr, 2 float4 per array -----------------------------
#pragma unroll
        for (int r = 0; r < 2; ++r) {
            int idx = r * 2048 + tid * 4;
            int v = idx >> 6, o = idx & 63;
            float aL = S->s0[v], aH = S->s1[v];
            float4 oh;
            oh.x = felu(fmaf(aL, S->h0[o + 0], aH * S->h1[o + 0]));
            oh.y = felu(fmaf(aL, S->h0[o + 1], aH * S->h1[o + 1]));
            oh.z = felu(fmaf(aL, S->h0[o + 2], aH * S->h1[o + 2]));
            oh.w = felu(fmaf(aL, S->h0[o + 3], aH * S->h1[o + 3]));
            *reinterpret_cast<float4*>(out_h + obase + idx) = oh;
            float av = (o < 32) ? aL : aH;
            float4 oa; oa.x = av; oa.y = av; oa.z = av; oa.w = av;
            *reinterpret_cast<float4*>(out_att + obase + idx) = oa;
        }
    } else {
        // ---- stage A: wa0/wa1 dots (tid<128) || Y-fold (tid in [128,384)) --
        if (tid < 128) {
            int c = tid & 63;
            const float* a2 = S->a_s + ((tid >> 6) << 6);
            const float* wr = S->Ws + c * TS;
            float d0 = 0.f, d1 = 0.f, d2 = 0.f, d3 = 0.f;
#pragma unroll
            for (int o = 0; o < 64; o += 4) {
                d0 = fmaf(wr[o + 0], a2[o + 0], d0);
                d1 = fmaf(wr[o + 1], a2[o + 1], d1);
                d2 = fmaf(wr[o + 2], a2[o + 2], d2);
                d3 = fmaf(wr[o + 3], a2[o + 3], d3);
            }
            ((tid < 64) ? S->wa0 : S->wa1)[c] = (d0 + d1) + (d2 + d3);
        } else if (tid < 384) {
            // Y[j,c] = XC[j,c]+XC[j+32,c]: 2048 elems / 256 threads
            int t2 = tid - 128;
            int c = t2 & 63, jb = (t2 >> 6) * 8;
#pragma unroll
            for (int k = 0; k < 8; ++k) {
                int j = jb + k;
                S->Y[j * TS + c] = S->XC[j * TS + c] + S->XC[(j + 32) * TS + c];
            }
        }
        __syncthreads();
        // ---- stage B: pe/qo dots (tid<128) ----------------------------------
        if (tid < 128) {
            int g = tid >> 5, j = tid & 31;
            int par = g & 1;                     // 0: p@even (wa0), 1: q@odd
            const float* row = ((g < 2) ? S->X0 : S->X1) + (2 * j + par) * TS;
            const float* wv  = par ? S->wa1 : S->wa0;
            float a0 = 0.f, a1 = 0.f;
#pragma unroll
            for (int c = 0; c < 64; c += 2) {
                a0 = fmaf(row[c],     wv[c],     a0);
                a1 = fmaf(row[c + 1], wv[c + 1], a1);
            }
            ((g < 2) ? S->r0 : S->r1)[par * 32 + j] = a0 + a1;
        }
        __syncthreads();
        // ---- stage C: 32-value softmax, rows lo/hi (tid<64) ------------------
        if (tid < 64) {
            int lane = tid & 31;
            const float* rr = (tid >= 32) ? S->r1 : S->r0;
            float e = lrelu(rr[lane] + rr[32 + lane]);
            float m = wmax(e);
            float x = __expf(e - m);
            float den = __fdividef(1.0f, 2.0f * wsum(x));
            ((tid >= 32) ? S->s1 : S->s0)[lane] = x * den;
        }
        __syncthreads();
        // ---- stage D: u = s@Y (tid<128) || out_att stores (tid>=128) --------
        if (tid < 128) {
            int c = tid & 63; bool hi = (tid >= 64);
            const float* s   = hi ? S->s1 : S->s0;
            const float* col = S->Y + c;
            float a0 = 0.f, a1 = 0.f;
#pragma unroll
            for (int j = 0; j < 32; j += 2) {
                a0 = fmaf(s[j],     col[(j + 0) * TS], a0);
                a1 = fmaf(s[j + 1], col[(j + 1) * TS], a1);
            }
            (hi ? S->v1 : S->v0)[c] = a0 + a1;
        } else {
            // 1024 float4 over 384 threads: t2 in [0,384), ceil -> 3 iters
            int t2 = tid - 128;
#pragma unroll
            for (int r = 0; r < 3; ++r) {
                int q = r * 384 + t2;
                if (q < 1024) {
                    int idx = q * 4;
                    int v = idx >> 6, ob = idx & 31;
                    const float* ar = (v < 32) ? S->s0 : S->s1;
                    float4 oa;
                    oa.x = ar[ob]; oa.y = ar[ob + 1]; oa.z = ar[ob + 2]; oa.w = ar[ob + 3];
                    *reinterpret_cast<float4*>(out_att + obase + idx) = oa;
                }
            }
        }
        __syncthreads();
        // ---- stage E: hp = u@W, elu (tid<128) --------------------------------
        if (tid < 128) {
            int o = tid & 63; bool hi = (tid >= 64);
            const float* vv = hi ? S->v1 : S->v0;
            float d0 = 0.f, d1 = 0.f, d2 = 0.f, d3 = 0.f;
#pragma unroll
            for (int c = 0; c < 64; c += 4) {
                d0 = fmaf(vv[c + 0], S->Ws[(c + 0) * TS + o], d0);
                d1 = fmaf(vv[c + 1], S->Ws[(c + 1) * TS + o], d1);
                d2 = fmaf(vv[c + 2], S->Ws[(c + 2) * TS + o], d2);
                d3 = fmaf(vv[c + 3], S->Ws[(c + 3) * TS + o], d3);
            }
            (hi ? S->h1 : S->h0)[o] = felu((d0 + d1) + (d2 + d3));
        }
        __syncthreads();
        // ---- write out_h: 512 thr, 2 float4 each -----------------------------
#pragma unroll
        for (int r = 0; r < 2; ++r) {
            int idx = r * 2048 + tid * 4;
            int v = idx >> 6, o = idx & 63;
            const float* hr = (v < 32) ? S->h0 : S->h1;
            float4 oh; oh.x = hr[o]; oh.y = hr[o + 1]; oh.z = hr[o + 2]; oh.w = hr[o + 3];
            *reinterpret_cast<float4*>(out_h + obase + idx) = oh;
        }
    }
}

extern "C" void kernel_launch(void* const* d_in, const int* in_sizes, int n_in,
                              void* d_out, int out_size) {
    const float* inp = (const float*)d_in[0];   // [16,12,64,64]
    // d_in[1] = adj : dead code
    const float* W   = (const float*)d_in[2];   // [64,64]
    const float* a   = (const float*)d_in[3];   // [128,1]
    float* out = (float*)d_out;
    int nt = in_sizes[0] / 4096;                // 192
    int smem = (int)sizeof(Smem);
    static int smem_set = 0;
    if (!smem_set) {
        cudaFuncSetAttribute(gat_kernel, cudaFuncAttributeMaxDynamicSharedMemorySize, smem);
        smem_set = 1;
    }
    gat_kernel<<<nt, 512, smem>>>(inp, W, a, out, out + out_size / 2);
}